// round 7
// baseline (speedup 1.0000x reference)
#include <cuda_runtime.h>

// Shapes: B=512, T=128, N=128, H=256
#define BB 512
#define TT 128
#define NN 128
#define HH 256

__device__ float g_xW[TT * BB * HH];   // [s][b][h]
__device__ float g_Hs2[TT * HH * BB];  // [s][h][b]
__device__ float g_Q[TT * BB * TT];    // [s][b][t]
__device__ float g_preT[BB * TT * NN]; // [b][t][n]

typedef unsigned long long ull;

__device__ __forceinline__ ull dup2(float x) {
    ull r; asm("mov.b64 %0, {%1, %1};" : "=l"(r) : "f"(x)); return r;
}
__device__ __forceinline__ ull ffma2(ull a, ull b, ull c) {
    ull d; asm("fma.rn.f32x2 %0, %1, %2, %3;" : "=l"(d) : "l"(a), "l"(b), "l"(c)); return d;
}
__device__ __forceinline__ void unpk(ull p, float& x, float& y) {
    asm("mov.b64 {%0, %1}, %2;" : "=f"(x), "=f"(y) : "l"(p));
}
union F4U { float4 v; ull u[2]; };

__device__ __forceinline__ float tanh_fast(float x) {
    float y; asm("tanh.approx.f32 %0, %1;" : "=f"(y) : "f"(x)); return y;
}

// ---------------------------------------------------------------------------
// K_xw3: xW[m][h] = data-row(m) @ Wx + b.  (unchanged)
// ---------------------------------------------------------------------------
__global__ __launch_bounds__(256, 2) void k_xw3(const float* __restrict__ data,
                                                const float* __restrict__ Wx,
                                                const float* __restrict__ bvec) {
    __shared__ float sA[2][16][132];
    __shared__ float sB[2][16][128];
    int m0 = blockIdx.x * 128;
    int h0 = blockIdx.y * 128;
    int tid = threadIdx.x;

    int am = tid >> 1;
    int ak = (tid & 1) * 8;
    int m = m0 + am;
    int s = m >> 9, b = m & 511;
    const float* aptr = data + (size_t)b * (TT * NN) + s * NN + ak;
    int kb = tid >> 5;
    int nb = (tid & 31) * 4;
    const float* bptr = Wx + (size_t)kb * HH + h0 + nb;

    float4 pa0 = *(const float4*)(aptr);
    float4 pa1 = *(const float4*)(aptr + 4);
    float4 pb0 = *(const float4*)(bptr);
    float4 pb1 = *(const float4*)(bptr + 8 * HH);
    {
        float av[8] = {pa0.x, pa0.y, pa0.z, pa0.w, pa1.x, pa1.y, pa1.z, pa1.w};
#pragma unroll
        for (int jj = 0; jj < 8; ++jj) sA[0][ak + jj][am] = av[jj];
        *(float4*)&sB[0][kb][nb] = pb0;
        *(float4*)&sB[0][kb + 8][nb] = pb1;
    }
    __syncthreads();

    int ty = tid >> 4, tx = tid & 15;
    int mr = ty * 8, nr = tx * 8;
    ull acc[8][4] = {};

#pragma unroll 2
    for (int c = 0; c < 8; ++c) {
        if (c + 1 < 8) {
            int k0 = (c + 1) * 16;
            pa0 = *(const float4*)(aptr + k0);
            pa1 = *(const float4*)(aptr + k0 + 4);
            pb0 = *(const float4*)(bptr + (size_t)k0 * HH);
            pb1 = *(const float4*)(bptr + (size_t)(k0 + 8) * HH);
        }
        int buf = c & 1;
#pragma unroll
        for (int k = 0; k < 16; ++k) {
            float4 a0 = *(const float4*)&sA[buf][k][mr];
            float4 a1 = *(const float4*)&sA[buf][k][mr + 4];
            F4U b0u, b1u;
            b0u.v = *(const float4*)&sB[buf][k][nr];
            b1u.v = *(const float4*)&sB[buf][k][nr + 4];
            float av[8] = {a0.x, a0.y, a0.z, a0.w, a1.x, a1.y, a1.z, a1.w};
            ull bp[4] = {b0u.u[0], b0u.u[1], b1u.u[0], b1u.u[1]};
#pragma unroll
            for (int r = 0; r < 8; ++r) {
                ull ad = dup2(av[r]);
#pragma unroll
                for (int p = 0; p < 4; ++p) acc[r][p] = ffma2(ad, bp[p], acc[r][p]);
            }
        }
        if (c + 1 < 8) {
            int nbuf = (c + 1) & 1;
            float av[8] = {pa0.x, pa0.y, pa0.z, pa0.w, pa1.x, pa1.y, pa1.z, pa1.w};
#pragma unroll
            for (int jj = 0; jj < 8; ++jj) sA[nbuf][ak + jj][am] = av[jj];
            *(float4*)&sB[nbuf][kb][nb] = pb0;
            *(float4*)&sB[nbuf][kb + 8][nb] = pb1;
            __syncthreads();
        }
    }

    float bias[8];
#pragma unroll
    for (int cc = 0; cc < 8; ++cc) bias[cc] = __ldg(&bvec[h0 + nr + cc]);
#pragma unroll
    for (int r = 0; r < 8; ++r) {
        float o[8];
        unpk(acc[r][0], o[0], o[1]);
        unpk(acc[r][1], o[2], o[3]);
        unpk(acc[r][2], o[4], o[5]);
        unpk(acc[r][3], o[6], o[7]);
        float* op = g_xW + (size_t)(m0 + mr + r) * HH + h0 + nr;
        float4 o0 = {o[0] + bias[0], o[1] + bias[1], o[2] + bias[2], o[3] + bias[3]};
        float4 o1 = {o[4] + bias[4], o[5] + bias[5], o[6] + bias[6], o[7] + bias[7]};
        *(float4*)&op[0] = o0;
        *(float4*)&op[4] = o1;
    }
}

// ---------------------------------------------------------------------------
// K_pre3: preT[b][t][n]  (unchanged)
// ---------------------------------------------------------------------------
__global__ __launch_bounds__(256, 2) void k_pre3(const float* __restrict__ data,
                                                 const float* __restrict__ W1,
                                                 const float* __restrict__ b1) {
    __shared__ float sA[2][16][128];
    __shared__ float sB[2][16][128];
    int b = blockIdx.x;
    int tid = threadIdx.x;

    int kb = tid >> 5;
    int nb = (tid & 31) * 4;
    const float* aptr = W1 + (size_t)kb * TT + nb;
    const float* bptr = data + (size_t)b * (TT * NN) + (size_t)kb * NN + nb;

    float4 pa0 = *(const float4*)(aptr);
    float4 pa1 = *(const float4*)(aptr + 8 * TT);
    float4 pb0 = *(const float4*)(bptr);
    float4 pb1 = *(const float4*)(bptr + 8 * NN);
    *(float4*)&sA[0][kb][nb] = pa0;
    *(float4*)&sA[0][kb + 8][nb] = pa1;
    *(float4*)&sB[0][kb][nb] = pb0;
    *(float4*)&sB[0][kb + 8][nb] = pb1;
    __syncthreads();

    int ty = tid >> 4, tx = tid & 15;
    int mr = ty * 8, nr = tx * 8;
    ull acc[8][4] = {};

#pragma unroll 2
    for (int c = 0; c < 8; ++c) {
        if (c + 1 < 8) {
            int k0 = (c + 1) * 16;
            pa0 = *(const float4*)(aptr + (size_t)k0 * TT);
            pa1 = *(const float4*)(aptr + (size_t)(k0 + 8) * TT);
            pb0 = *(const float4*)(bptr + (size_t)k0 * NN);
            pb1 = *(const float4*)(bptr + (size_t)(k0 + 8) * NN);
        }
        int buf = c & 1;
#pragma unroll
        for (int k = 0; k < 16; ++k) {
            float4 a0 = *(const float4*)&sA[buf][k][mr];
            float4 a1 = *(const float4*)&sA[buf][k][mr + 4];
            F4U b0u, b1u;
            b0u.v = *(const float4*)&sB[buf][k][nr];
            b1u.v = *(const float4*)&sB[buf][k][nr + 4];
            float av[8] = {a0.x, a0.y, a0.z, a0.w, a1.x, a1.y, a1.z, a1.w};
            ull bp[4] = {b0u.u[0], b0u.u[1], b1u.u[0], b1u.u[1]};
#pragma unroll
            for (int r = 0; r < 8; ++r) {
                ull ad = dup2(av[r]);
#pragma unroll
                for (int p = 0; p < 4; ++p) acc[r][p] = ffma2(ad, bp[p], acc[r][p]);
            }
        }
        if (c + 1 < 8) {
            int nbuf = (c + 1) & 1;
            *(float4*)&sA[nbuf][kb][nb] = pa0;
            *(float4*)&sA[nbuf][kb + 8][nb] = pa1;
            *(float4*)&sB[nbuf][kb][nb] = pb0;
            *(float4*)&sB[nbuf][kb + 8][nb] = pb1;
            __syncthreads();
        }
    }

#pragma unroll
    for (int r = 0; r < 8; ++r) {
        int t = mr + r;
        float bt = __ldg(&b1[t]);
        float o[8];
        unpk(acc[r][0], o[0], o[1]);
        unpk(acc[r][1], o[2], o[3]);
        unpk(acc[r][2], o[4], o[5]);
        unpk(acc[r][3], o[6], o[7]);
        float* op = g_preT + (size_t)b * (TT * NN) + (size_t)t * NN + nr;
        float4 o0 = {o[0] + bt, o[1] + bt, o[2] + bt, o[3] + bt};
        float4 o1 = {o[4] + bt, o[5] + bt, o[6] + bt, o[7] + bt};
        *(float4*)&op[0] = o0;
        *(float4*)&op[4] = o1;
    }
}

// ---------------------------------------------------------------------------
// K_rnn8: 128 CTAs x 4 rows, 1024 threads, symmetric 4-way k-split.
// Quarter q owns k in [64q, 64q+64): 48 k-rows from smem (192 rows total,
// 192KB) + 16 k-rows from per-thread registers. tanh via MUFU (validated
// accurate by k_att's 1.46e-6 rel_err). q3 folds xW into its partial;
// q0 stores h to gmem, q1 stores h to next smem buffer. 2 barriers/step.
// ---------------------------------------------------------------------------
__global__ __launch_bounds__(1024, 1) void k_rnn8(const float* __restrict__ h0,
                                                  const float* __restrict__ Wh) {
    extern __shared__ float sm[];
    float* sW = sm;             // [192][256]: row q*48+kk <-> Wh row 64q+kk
    float* sh = sm + 192 * 256; // [2][256][4]
    float* sred = sh + 2048;    // [4][256][4]
    int b0 = blockIdx.x * 4;
    int tid = threadIdx.x;
    int j = tid & 255;
    int q = tid >> 8;

    // smem weights: coalesced float4 fill
    for (int i = tid; i < 192 * 64; i += 1024) {
        int row = i >> 6;
        int c4 = (i & 63) * 4;
        int gr = ((row / 48) << 6) + row % 48;  // 64*(row/48) + row%48
        *(float4*)&sW[row * 256 + c4] = *(const float4*)&Wh[(size_t)gr * HH + c4];
    }
    // reg weights: k = 64q + 48 + c
    float wr[16];
    {
        const float* wp = Wh + (size_t)(q * 64 + 48) * HH + j;
#pragma unroll
        for (int c = 0; c < 16; ++c) wr[c] = wp[(size_t)c * HH];
    }
    if (q == 0) {
        float4 h4;
        h4.x = h0[(size_t)(b0 + 0) * HH + j];
        h4.y = h0[(size_t)(b0 + 1) * HH + j];
        h4.z = h0[(size_t)(b0 + 2) * HH + j];
        h4.w = h0[(size_t)(b0 + 3) * HH + j];
        *(float4*)&sh[j * 4] = h4;
    }
    __syncthreads();

    // q3: xW prefetch registers
    float nx0 = 0.f, nx1 = 0.f, nx2 = 0.f, nx3 = 0.f;
    if (q == 3) {
        const float* xw = g_xW + (size_t)b0 * HH + j;
        nx0 = xw[0]; nx1 = xw[HH]; nx2 = xw[2 * HH]; nx3 = xw[3 * HH];
    }

    const float* swj = sW + (size_t)(q * 48) * 256 + j;  // smem weight column
    int hbase = q * 64;                                   // h index base
    float* myred = sred + q * 1024;

    for (int s = 0; s < TT; ++s) {
        const float* shc = sh + (s & 1) * 1024;
        float* shn = sh + (1 - (s & 1)) * 1024;

        float a0, a1, a2, a3;
        if (q == 3) {
            a0 = nx0; a1 = nx1; a2 = nx2; a3 = nx3;
            if (s + 1 < TT) {
                const float* xw = g_xW + (size_t)(s + 1) * (BB * HH) + (size_t)b0 * HH + j;
                nx0 = xw[0]; nx1 = xw[HH]; nx2 = xw[2 * HH]; nx3 = xw[3 * HH];
            }
        } else {
            a0 = a1 = a2 = a3 = 0.f;
        }
        float c0 = 0.f, c1 = 0.f, c2 = 0.f, c3 = 0.f;

        // smem-weight part: 48 k
#pragma unroll 12
        for (int kk = 0; kk < 48; ++kk) {
            float w = swj[kk * 256];
            float4 h4 = *(const float4*)&shc[(hbase + kk) * 4];
            a0 += h4.x * w; a1 += h4.y * w; a2 += h4.z * w; a3 += h4.w * w;
        }
        // reg-weight part: 16 k
#pragma unroll
        for (int c = 0; c < 16; ++c) {
            float w = wr[c];
            float4 h4 = *(const float4*)&shc[(hbase + 48 + c) * 4];
            c0 += h4.x * w; c1 += h4.y * w; c2 += h4.z * w; c3 += h4.w * w;
        }
        *(float4*)&myred[j * 4] = make_float4(a0 + c0, a1 + c1, a2 + c2, a3 + c3);
        __syncthreads();  // partials visible

        float4 p0 = *(const float4*)&sred[j * 4];
        float4 p1 = *(const float4*)&sred[1024 + j * 4];
        float4 p2 = *(const float4*)&sred[2048 + j * 4];
        float4 p3 = *(const float4*)&sred[3072 + j * 4];
        float4 h4o;
        h4o.x = tanh_fast(p0.x + p1.x + p2.x + p3.x);
        h4o.y = tanh_fast(p0.y + p1.y + p2.y + p3.y);
        h4o.z = tanh_fast(p0.z + p1.z + p2.z + p3.z);
        h4o.w = tanh_fast(p0.w + p1.w + p2.w + p3.w);
        if (q == 0) {
            *(float4*)&g_Hs2[((size_t)s * HH + j) * BB + b0] = h4o;
        } else if (q == 1) {
            *(float4*)&shn[j * 4] = h4o;
        }
        __syncthreads();  // h(s) visible before next step
    }
}

// ---------------------------------------------------------------------------
// K_q3: Q[m][t] = Hs-row(m) @ W2 + b2, reading transposed g_Hs2. (unchanged)
// ---------------------------------------------------------------------------
__global__ __launch_bounds__(256, 2) void k_q3(const float* __restrict__ W2,
                                               const float* __restrict__ b2) {
    __shared__ float sA[2][16][132];
    __shared__ float sB[2][16][128];
    int m0 = blockIdx.x * 128;
    int s = m0 >> 9, b0m = m0 & 511;
    int tid = threadIdx.x;

    int kk0 = tid >> 5;
    int mmo = (tid & 31) * 4;
    int kk1 = kk0 + 8;
    const float* aB = g_Hs2 + (size_t)s * HH * BB + b0m + mmo;
    int kb = tid >> 5;
    int nb = (tid & 31) * 4;
    const float* bptr = W2 + (size_t)kb * TT + nb;

    float4 pa0 = *(const float4*)&aB[(size_t)kk0 * BB];
    float4 pa1 = *(const float4*)&aB[(size_t)kk1 * BB];
    float4 pb0 = *(const float4*)(bptr);
    float4 pb1 = *(const float4*)(bptr + 8 * TT);
    *(float4*)&sA[0][kk0][mmo] = pa0;
    *(float4*)&sA[0][kk1][mmo] = pa1;
    *(float4*)&sB[0][kb][nb] = pb0;
    *(float4*)&sB[0][kb + 8][nb] = pb1;
    __syncthreads();

    int ty = tid >> 4, tx = tid & 15;
    int mr = ty * 8, nr = tx * 8;
    ull acc[8][4] = {};

#pragma unroll 2
    for (int c = 0; c < 16; ++c) {
        if (c + 1 < 16) {
            int k0 = (c + 1) * 16;
            pa0 = *(const float4*)&aB[(size_t)(k0 + kk0) * BB];
            pa1 = *(const float4*)&aB[(size_t)(k0 + kk1) * BB];
            pb0 = *(const float4*)(bptr + (size_t)k0 * TT);
            pb1 = *(const float4*)(bptr + (size_t)(k0 + 8) * TT);
        }
        int buf = c & 1;
#pragma unroll
        for (int k = 0; k < 16; ++k) {
            float4 a0 = *(const float4*)&sA[buf][k][mr];
            float4 a1 = *(const float4*)&sA[buf][k][mr + 4];
            F4U b0u, b1u;
            b0u.v = *(const float4*)&sB[buf][k][nr];
            b1u.v = *(const float4*)&sB[buf][k][nr + 4];
            float av[8] = {a0.x, a0.y, a0.z, a0.w, a1.x, a1.y, a1.z, a1.w};
            ull bp[4] = {b0u.u[0], b0u.u[1], b1u.u[0], b1u.u[1]};
#pragma unroll
            for (int r = 0; r < 8; ++r) {
                ull ad = dup2(av[r]);
#pragma unroll
                for (int p = 0; p < 4; ++p) acc[r][p] = ffma2(ad, bp[p], acc[r][p]);
            }
        }
        if (c + 1 < 16) {
            int nbuf = (c + 1) & 1;
            *(float4*)&sA[nbuf][kk0][mmo] = pa0;
            *(float4*)&sA[nbuf][kk1][mmo] = pa1;
            *(float4*)&sB[nbuf][kb][nb] = pb0;
            *(float4*)&sB[nbuf][kb + 8][nb] = pb1;
            __syncthreads();
        }
    }

    float bias[8];
#pragma unroll
    for (int cc = 0; cc < 8; ++cc) bias[cc] = __ldg(&b2[nr + cc]);
#pragma unroll
    for (int r = 0; r < 8; ++r) {
        float o[8];
        unpk(acc[r][0], o[0], o[1]);
        unpk(acc[r][1], o[2], o[3]);
        unpk(acc[r][2], o[4], o[5]);
        unpk(acc[r][3], o[6], o[7]);
        float* op = g_Q + (size_t)(m0 + mr + r) * TT + nr;
        float4 o0 = {o[0] + bias[0], o[1] + bias[1], o[2] + bias[2], o[3] + bias[3]};
        float4 o1 = {o[4] + bias[4], o[5] + bias[5], o[6] + bias[6], o[7] + bias[7]};
        *(float4*)&op[0] = o0;
        *(float4*)&op[4] = o1;
    }
}

// ---------------------------------------------------------------------------
// K_att3: scores + softmax + fused output multiply (unchanged; MUFU-bound).
// ---------------------------------------------------------------------------
__global__ __launch_bounds__(256) void k_att3(const float* __restrict__ data,
                                              const float* __restrict__ Wv,
                                              float* __restrict__ out) {
    extern __shared__ float sm[];
    float* sP = sm;
    float* sQ = sm + 16384;
    float* sWv = sQ + 256;
    float* sred = sWv + 128;
    int b = blockIdx.x >> 1;
    int shalf = blockIdx.x & 1;
    int tid = threadIdx.x;

    const float4* gP = (const float4*)(g_preT + (size_t)b * (TT * NN));
    for (int i = tid; i < 4096; i += 256) ((float4*)sP)[i] = gP[i];
    if (tid < 128) sWv[tid] = Wv[tid];
    __syncthreads();

    int n = tid & 127;
    int grp = tid >> 7;
    int lane = tid & 31;
    int wig = (tid >> 5) & 3;

    for (int si = 0; si < 32; ++si) {
        int s = shalf * 64 + si * 2 + grp;
        sQ[tid] = g_Q[(size_t)s * (BB * TT) + b * TT + n];
        __syncthreads();

        const float* qrow = sQ + grp * 128;
        float e = 0.f;
#pragma unroll 8
        for (int t = 0; t < 128; ++t) {
            e += sWv[t] * tanh_fast(sP[t * 128 + n] + qrow[t]);
        }

        float ex = __expf(e);
        float sum = ex;
#pragma unroll
        for (int o = 16; o; o >>= 1) sum += __shfl_xor_sync(0xFFFFFFFFu, sum, o);
        if (lane == 0) sred[grp * 4 + wig] = sum;
        __syncthreads();
        sum = sred[grp * 4 + 0] + sred[grp * 4 + 1] + sred[grp * 4 + 2] + sred[grp * 4 + 3];
        float alpha = ex / sum;

        int bp = 4 * s + (b >> 7);
        int tp = b & 127;
        size_t idx = (size_t)bp * (TT * NN) + tp * NN + n;
        out[idx] = data[idx] * alpha;
        __syncthreads();
    }
}

// ---------------------------------------------------------------------------
extern "C" void kernel_launch(void* const* d_in, const int* in_sizes, int n_in,
                              void* d_out, int out_size) {
    const float* data = (const float*)d_in[0];
    const float* h0 = (const float*)d_in[1];
    const float* Wx = (const float*)d_in[2];
    const float* Wh = (const float*)d_in[3];
    const float* bvec = (const float*)d_in[4];
    const float* W1 = (const float*)d_in[5];
    const float* b1 = (const float*)d_in[6];
    const float* W2 = (const float*)d_in[7];
    const float* b2 = (const float*)d_in[8];
    const float* Wv = (const float*)d_in[9];
    float* out = (float*)d_out;

    const int SM_RNN = (192 * 256 + 2048 + 4096) * 4;    // 221,184 B
    const int SM_ATT = (128 * 128 + 256 + 128 + 8) * 4;  // ~66 KB

    cudaFuncSetAttribute(k_rnn8, cudaFuncAttributeMaxDynamicSharedMemorySize, SM_RNN);
    cudaFuncSetAttribute(k_att3, cudaFuncAttributeMaxDynamicSharedMemorySize, SM_ATT);

    k_xw3<<<dim3((TT * BB) / 128, HH / 128), 256>>>(data, Wx, bvec);
    k_pre3<<<BB, 256>>>(data, W1, b1);
    k_rnn8<<<BB / 4, 1024, SM_RNN>>>(h0, Wh);
    k_q3<<<(TT * BB) / 128, 256>>>(W2, b2);
    k_att3<<<BB * 2, 256, SM_ATT>>>(data, Wv, out);
}

// round 8
// speedup vs baseline: 1.0655x; 1.0655x over previous
#include <cuda_runtime.h>

// Shapes: B=512, T=128, N=128, H=256
#define BB 512
#define TT 128
#define NN 128
#define HH 256

__device__ float g_xW[TT * BB * HH];   // [s][b][h]
__device__ float g_Hs2[TT * HH * BB];  // [s][h][b]
__device__ float g_Q[TT * BB * TT];    // [s][b][t]
__device__ float g_preT[BB * TT * NN]; // [b][t][n]

typedef unsigned long long ull;

__device__ __forceinline__ ull pack2(float x, float y) {
    ull r; asm("mov.b64 %0, {%1, %2};" : "=l"(r) : "f"(x), "f"(y)); return r;
}
__device__ __forceinline__ ull dup2(float x) {
    ull r; asm("mov.b64 %0, {%1, %1};" : "=l"(r) : "f"(x)); return r;
}
__device__ __forceinline__ ull ffma2(ull a, ull b, ull c) {
    ull d; asm("fma.rn.f32x2 %0, %1, %2, %3;" : "=l"(d) : "l"(a), "l"(b), "l"(c)); return d;
}
__device__ __forceinline__ ull fadd2(ull a, ull b) {
    ull d; asm("add.rn.f32x2 %0, %1, %2;" : "=l"(d) : "l"(a), "l"(b)); return d;
}
__device__ __forceinline__ void unpk(ull p, float& x, float& y) {
    asm("mov.b64 {%0, %1}, %2;" : "=f"(x), "=f"(y) : "l"(p));
}
union F4U { float4 v; ull u[2]; };

__device__ __forceinline__ float tanh_fast(float x) {
    float y; asm("tanh.approx.f32 %0, %1;" : "=f"(y) : "f"(x)); return y;
}

// ---------------------------------------------------------------------------
// K_xw3: xW[m][h] = data-row(m) @ Wx + b.  (unchanged)
// ---------------------------------------------------------------------------
__global__ __launch_bounds__(256, 2) void k_xw3(const float* __restrict__ data,
                                                const float* __restrict__ Wx,
                                                const float* __restrict__ bvec) {
    __shared__ float sA[2][16][132];
    __shared__ float sB[2][16][128];
    int m0 = blockIdx.x * 128;
    int h0 = blockIdx.y * 128;
    int tid = threadIdx.x;

    int am = tid >> 1;
    int ak = (tid & 1) * 8;
    int m = m0 + am;
    int s = m >> 9, b = m & 511;
    const float* aptr = data + (size_t)b * (TT * NN) + s * NN + ak;
    int kb = tid >> 5;
    int nb = (tid & 31) * 4;
    const float* bptr = Wx + (size_t)kb * HH + h0 + nb;

    float4 pa0 = *(const float4*)(aptr);
    float4 pa1 = *(const float4*)(aptr + 4);
    float4 pb0 = *(const float4*)(bptr);
    float4 pb1 = *(const float4*)(bptr + 8 * HH);
    {
        float av[8] = {pa0.x, pa0.y, pa0.z, pa0.w, pa1.x, pa1.y, pa1.z, pa1.w};
#pragma unroll
        for (int jj = 0; jj < 8; ++jj) sA[0][ak + jj][am] = av[jj];
        *(float4*)&sB[0][kb][nb] = pb0;
        *(float4*)&sB[0][kb + 8][nb] = pb1;
    }
    __syncthreads();

    int ty = tid >> 4, tx = tid & 15;
    int mr = ty * 8, nr = tx * 8;
    ull acc[8][4] = {};

#pragma unroll 2
    for (int c = 0; c < 8; ++c) {
        if (c + 1 < 8) {
            int k0 = (c + 1) * 16;
            pa0 = *(const float4*)(aptr + k0);
            pa1 = *(const float4*)(aptr + k0 + 4);
            pb0 = *(const float4*)(bptr + (size_t)k0 * HH);
            pb1 = *(const float4*)(bptr + (size_t)(k0 + 8) * HH);
        }
        int buf = c & 1;
#pragma unroll
        for (int k = 0; k < 16; ++k) {
            float4 a0 = *(const float4*)&sA[buf][k][mr];
            float4 a1 = *(const float4*)&sA[buf][k][mr + 4];
            F4U b0u, b1u;
            b0u.v = *(const float4*)&sB[buf][k][nr];
            b1u.v = *(const float4*)&sB[buf][k][nr + 4];
            float av[8] = {a0.x, a0.y, a0.z, a0.w, a1.x, a1.y, a1.z, a1.w};
            ull bp[4] = {b0u.u[0], b0u.u[1], b1u.u[0], b1u.u[1]};
#pragma unroll
            for (int r = 0; r < 8; ++r) {
                ull ad = dup2(av[r]);
#pragma unroll
                for (int p = 0; p < 4; ++p) acc[r][p] = ffma2(ad, bp[p], acc[r][p]);
            }
        }
        if (c + 1 < 8) {
            int nbuf = (c + 1) & 1;
            float av[8] = {pa0.x, pa0.y, pa0.z, pa0.w, pa1.x, pa1.y, pa1.z, pa1.w};
#pragma unroll
            for (int jj = 0; jj < 8; ++jj) sA[nbuf][ak + jj][am] = av[jj];
            *(float4*)&sB[nbuf][kb][nb] = pb0;
            *(float4*)&sB[nbuf][kb + 8][nb] = pb1;
            __syncthreads();
        }
    }

    float bias[8];
#pragma unroll
    for (int cc = 0; cc < 8; ++cc) bias[cc] = __ldg(&bvec[h0 + nr + cc]);
#pragma unroll
    for (int r = 0; r < 8; ++r) {
        float o[8];
        unpk(acc[r][0], o[0], o[1]);
        unpk(acc[r][1], o[2], o[3]);
        unpk(acc[r][2], o[4], o[5]);
        unpk(acc[r][3], o[6], o[7]);
        float* op = g_xW + (size_t)(m0 + mr + r) * HH + h0 + nr;
        float4 o0 = {o[0] + bias[0], o[1] + bias[1], o[2] + bias[2], o[3] + bias[3]};
        float4 o1 = {o[4] + bias[4], o[5] + bias[5], o[6] + bias[6], o[7] + bias[7]};
        *(float4*)&op[0] = o0;
        *(float4*)&op[4] = o1;
    }
}

// ---------------------------------------------------------------------------
// K_pre3: preT[b][t][n]  (unchanged)
// ---------------------------------------------------------------------------
__global__ __launch_bounds__(256, 2) void k_pre3(const float* __restrict__ data,
                                                 const float* __restrict__ W1,
                                                 const float* __restrict__ b1) {
    __shared__ float sA[2][16][128];
    __shared__ float sB[2][16][128];
    int b = blockIdx.x;
    int tid = threadIdx.x;

    int kb = tid >> 5;
    int nb = (tid & 31) * 4;
    const float* aptr = W1 + (size_t)kb * TT + nb;
    const float* bptr = data + (size_t)b * (TT * NN) + (size_t)kb * NN + nb;

    float4 pa0 = *(const float4*)(aptr);
    float4 pa1 = *(const float4*)(aptr + 8 * TT);
    float4 pb0 = *(const float4*)(bptr);
    float4 pb1 = *(const float4*)(bptr + 8 * NN);
    *(float4*)&sA[0][kb][nb] = pa0;
    *(float4*)&sA[0][kb + 8][nb] = pa1;
    *(float4*)&sB[0][kb][nb] = pb0;
    *(float4*)&sB[0][kb + 8][nb] = pb1;
    __syncthreads();

    int ty = tid >> 4, tx = tid & 15;
    int mr = ty * 8, nr = tx * 8;
    ull acc[8][4] = {};

#pragma unroll 2
    for (int c = 0; c < 8; ++c) {
        if (c + 1 < 8) {
            int k0 = (c + 1) * 16;
            pa0 = *(const float4*)(aptr + (size_t)k0 * TT);
            pa1 = *(const float4*)(aptr + (size_t)(k0 + 8) * TT);
            pb0 = *(const float4*)(bptr + (size_t)k0 * NN);
            pb1 = *(const float4*)(bptr + (size_t)(k0 + 8) * NN);
        }
        int buf = c & 1;
#pragma unroll
        for (int k = 0; k < 16; ++k) {
            float4 a0 = *(const float4*)&sA[buf][k][mr];
            float4 a1 = *(const float4*)&sA[buf][k][mr + 4];
            F4U b0u, b1u;
            b0u.v = *(const float4*)&sB[buf][k][nr];
            b1u.v = *(const float4*)&sB[buf][k][nr + 4];
            float av[8] = {a0.x, a0.y, a0.z, a0.w, a1.x, a1.y, a1.z, a1.w};
            ull bp[4] = {b0u.u[0], b0u.u[1], b1u.u[0], b1u.u[1]};
#pragma unroll
            for (int r = 0; r < 8; ++r) {
                ull ad = dup2(av[r]);
#pragma unroll
                for (int p = 0; p < 4; ++p) acc[r][p] = ffma2(ad, bp[p], acc[r][p]);
            }
        }
        if (c + 1 < 8) {
            int nbuf = (c + 1) & 1;
            *(float4*)&sA[nbuf][kb][nb] = pa0;
            *(float4*)&sA[nbuf][kb + 8][nb] = pa1;
            *(float4*)&sB[nbuf][kb][nb] = pb0;
            *(float4*)&sB[nbuf][kb + 8][nb] = pb1;
            __syncthreads();
        }
    }

#pragma unroll
    for (int r = 0; r < 8; ++r) {
        int t = mr + r;
        float bt = __ldg(&b1[t]);
        float o[8];
        unpk(acc[r][0], o[0], o[1]);
        unpk(acc[r][1], o[2], o[3]);
        unpk(acc[r][2], o[4], o[5]);
        unpk(acc[r][3], o[6], o[7]);
        float* op = g_preT + (size_t)b * (TT * NN) + (size_t)t * NN + nr;
        float4 o0 = {o[0] + bt, o[1] + bt, o[2] + bt, o[3] + bt};
        float4 o1 = {o[4] + bt, o[5] + bt, o[6] + bt, o[7] + bt};
        *(float4*)&op[0] = o0;
        *(float4*)&op[4] = o1;
    }
}

// ---------------------------------------------------------------------------
// K_rnn9: rnn6's weight residency (64k smem + 64k regs per kh-half; NO L2
// streaming) + f32x2 packed row-pair accumulators (a01, a23) + MUFU tanh
// (validated R7: rel_err 1.5e-6). 512 threads, 2 barriers/step.
// ---------------------------------------------------------------------------
__global__ __launch_bounds__(512, 1) void k_rnn9(const float* __restrict__ h0,
                                                 const float* __restrict__ Wh) {
    extern __shared__ float sm[];
    float* sWs = sm;            // [128][256]: rows 0..63 = Wh k 0..63; rows 64..127 = Wh k 128..191
    float* sh = sm + 32768;     // [2][256][4]
    float* sred = sh + 2048;    // [256][4]
    int b0 = blockIdx.x * 4;
    int tid = threadIdx.x;
    int j = tid & 255;
    int kh = tid >> 8;

    // smem weights (coalesced)
    for (int i = tid; i < 128 * 64; i += 512) {
        int row = i >> 6;
        int c4 = i & 63;
        int gr = (row < 64) ? row : (row + 64);
        ((float4*)sWs)[i] = *(const float4*)&Wh[(size_t)gr * HH + c4 * 4];
    }
    // Register weights: kh0 -> k in [64,128); kh1 -> k in [192,256)
    float wr[64];
    {
        const float* wp = Wh + (size_t)(kh * 128 + 64) * HH + j;
#pragma unroll
        for (int c = 0; c < 64; ++c) wr[c] = wp[(size_t)c * HH];
    }
    if (kh == 0) {
        float4 h4;
        h4.x = h0[(size_t)(b0 + 0) * HH + j];
        h4.y = h0[(size_t)(b0 + 1) * HH + j];
        h4.z = h0[(size_t)(b0 + 2) * HH + j];
        h4.w = h0[(size_t)(b0 + 3) * HH + j];
        *(float4*)&sh[j * 4] = h4;
    }
    __syncthreads();

    // xW prefetch (kh0 only), packed
    ull nx01 = 0, nx23 = 0;
    if (kh == 0) {
        const float* xw = g_xW + (size_t)b0 * HH + j;
        nx01 = pack2(xw[0], xw[HH]);
        nx23 = pack2(xw[2 * HH], xw[3 * HH]);
    }

    const float* swj = sWs + j;          // smem weight column for this j
    int smbase = kh * 64;                // smem w rows: kh0 -> 0..63, kh1 -> 64..127
    int hsm = kh * 128;                  // smem-half h offset
    int hrg = kh * 128 + 64;             // reg-half h offset

    for (int s = 0; s < TT; ++s) {
        const float* shc = sh + (s & 1) * 1024;
        float* shn = sh + (1 - (s & 1)) * 1024;

        ull a01, a23;
        if (kh == 0) {
            a01 = nx01; a23 = nx23;
            if (s + 1 < TT) {
                const float* xw = g_xW + (size_t)(s + 1) * (BB * HH) + (size_t)b0 * HH + j;
                nx01 = pack2(xw[0], xw[HH]);
                nx23 = pack2(xw[2 * HH], xw[3 * HH]);
            }
        } else {
            a01 = 0; a23 = 0;
        }
        ull c01 = 0, c23 = 0;

        // smem-weight half: 64 k
#pragma unroll 16
        for (int k = 0; k < 64; ++k) {
            float w = swj[(smbase + k) * 256];
            F4U hu; hu.v = *(const float4*)&shc[(hsm + k) * 4];
            ull wd = dup2(w);
            a01 = ffma2(hu.u[0], wd, a01);
            a23 = ffma2(hu.u[1], wd, a23);
        }
        // reg-weight half: 64 k
#pragma unroll
        for (int c = 0; c < 64; ++c) {
            ull wd = dup2(wr[c]);
            F4U hu; hu.v = *(const float4*)&shc[(hrg + c) * 4];
            c01 = ffma2(hu.u[0], wd, c01);
            c23 = ffma2(hu.u[1], wd, c23);
        }

        if (kh == 1) {
            F4U r;
            r.u[0] = fadd2(a01, c01);
            r.u[1] = fadd2(a23, c23);
            *(float4*)&sred[j * 4] = r.v;
        }
        __syncthreads();  // partials visible
        if (kh == 0) {
            F4U p; p.v = *(const float4*)&sred[j * 4];
            a01 = fadd2(fadd2(a01, c01), p.u[0]);
            a23 = fadd2(fadd2(a23, c23), p.u[1]);
            float x0, x1, x2, x3;
            unpk(a01, x0, x1);
            unpk(a23, x2, x3);
            float4 h4o = make_float4(tanh_fast(x0), tanh_fast(x1), tanh_fast(x2), tanh_fast(x3));
            *(float4*)&shn[j * 4] = h4o;
            *(float4*)&g_Hs2[((size_t)s * HH + j) * BB + b0] = h4o;
        }
        __syncthreads();  // h(s) visible before next step
    }
}

// ---------------------------------------------------------------------------
// K_q3: Q[m][t] = Hs-row(m) @ W2 + b2, reading transposed g_Hs2. (unchanged)
// ---------------------------------------------------------------------------
__global__ __launch_bounds__(256, 2) void k_q3(const float* __restrict__ W2,
                                               const float* __restrict__ b2) {
    __shared__ float sA[2][16][132];
    __shared__ float sB[2][16][128];
    int m0 = blockIdx.x * 128;
    int s = m0 >> 9, b0m = m0 & 511;
    int tid = threadIdx.x;

    int kk0 = tid >> 5;
    int mmo = (tid & 31) * 4;
    int kk1 = kk0 + 8;
    const float* aB = g_Hs2 + (size_t)s * HH * BB + b0m + mmo;
    int kb = tid >> 5;
    int nb = (tid & 31) * 4;
    const float* bptr = W2 + (size_t)kb * TT + nb;

    float4 pa0 = *(const float4*)&aB[(size_t)kk0 * BB];
    float4 pa1 = *(const float4*)&aB[(size_t)kk1 * BB];
    float4 pb0 = *(const float4*)(bptr);
    float4 pb1 = *(const float4*)(bptr + 8 * TT);
    *(float4*)&sA[0][kk0][mmo] = pa0;
    *(float4*)&sA[0][kk1][mmo] = pa1;
    *(float4*)&sB[0][kb][nb] = pb0;
    *(float4*)&sB[0][kb + 8][nb] = pb1;
    __syncthreads();

    int ty = tid >> 4, tx = tid & 15;
    int mr = ty * 8, nr = tx * 8;
    ull acc[8][4] = {};

#pragma unroll 2
    for (int c = 0; c < 16; ++c) {
        if (c + 1 < 16) {
            int k0 = (c + 1) * 16;
            pa0 = *(const float4*)&aB[(size_t)(k0 + kk0) * BB];
            pa1 = *(const float4*)&aB[(size_t)(k0 + kk1) * BB];
            pb0 = *(const float4*)(bptr + (size_t)k0 * TT);
            pb1 = *(const float4*)(bptr + (size_t)(k0 + 8) * TT);
        }
        int buf = c & 1;
#pragma unroll
        for (int k = 0; k < 16; ++k) {
            float4 a0 = *(const float4*)&sA[buf][k][mr];
            float4 a1 = *(const float4*)&sA[buf][k][mr + 4];
            F4U b0u, b1u;
            b0u.v = *(const float4*)&sB[buf][k][nr];
            b1u.v = *(const float4*)&sB[buf][k][nr + 4];
            float av[8] = {a0.x, a0.y, a0.z, a0.w, a1.x, a1.y, a1.z, a1.w};
            ull bp[4] = {b0u.u[0], b0u.u[1], b1u.u[0], b1u.u[1]};
#pragma unroll
            for (int r = 0; r < 8; ++r) {
                ull ad = dup2(av[r]);
#pragma unroll
                for (int p = 0; p < 4; ++p) acc[r][p] = ffma2(ad, bp[p], acc[r][p]);
            }
        }
        if (c + 1 < 16) {
            int nbuf = (c + 1) & 1;
            *(float4*)&sA[nbuf][kk0][mmo] = pa0;
            *(float4*)&sA[nbuf][kk1][mmo] = pa1;
            *(float4*)&sB[nbuf][kb][nb] = pb0;
            *(float4*)&sB[nbuf][kb + 8][nb] = pb1;
            __syncthreads();
        }
    }

    float bias[8];
#pragma unroll
    for (int cc = 0; cc < 8; ++cc) bias[cc] = __ldg(&b2[nr + cc]);
#pragma unroll
    for (int r = 0; r < 8; ++r) {
        float o[8];
        unpk(acc[r][0], o[0], o[1]);
        unpk(acc[r][1], o[2], o[3]);
        unpk(acc[r][2], o[4], o[5]);
        unpk(acc[r][3], o[6], o[7]);
        float* op = g_Q + (size_t)(m0 + mr + r) * TT + nr;
        float4 o0 = {o[0] + bias[0], o[1] + bias[1], o[2] + bias[2], o[3] + bias[3]};
        float4 o1 = {o[4] + bias[4], o[5] + bias[5], o[6] + bias[6], o[7] + bias[7]};
        *(float4*)&op[0] = o0;
        *(float4*)&op[4] = o1;
    }
}

// ---------------------------------------------------------------------------
// K_att3: scores + softmax + fused output multiply (unchanged; MUFU-bound).
// ---------------------------------------------------------------------------
__global__ __launch_bounds__(256) void k_att3(const float* __restrict__ data,
                                              const float* __restrict__ Wv,
                                              float* __restrict__ out) {
    extern __shared__ float sm[];
    float* sP = sm;
    float* sQ = sm + 16384;
    float* sWv = sQ + 256;
    float* sred = sWv + 128;
    int b = blockIdx.x >> 1;
    int shalf = blockIdx.x & 1;
    int tid = threadIdx.x;

    const float4* gP = (const float4*)(g_preT + (size_t)b * (TT * NN));
    for (int i = tid; i < 4096; i += 256) ((float4*)sP)[i] = gP[i];
    if (tid < 128) sWv[tid] = Wv[tid];
    __syncthreads();

    int n = tid & 127;
    int grp = tid >> 7;
    int lane = tid & 31;
    int wig = (tid >> 5) & 3;

    for (int si = 0; si < 32; ++si) {
        int s = shalf * 64 + si * 2 + grp;
        sQ[tid] = g_Q[(size_t)s * (BB * TT) + b * TT + n];
        __syncthreads();

        const float* qrow = sQ + grp * 128;
        float e = 0.f;
#pragma unroll 8
        for (int t = 0; t < 128; ++t) {
            e += sWv[t] * tanh_fast(sP[t * 128 + n] + qrow[t]);
        }

        float ex = __expf(e);
        float sum = ex;
#pragma unroll
        for (int o = 16; o; o >>= 1) sum += __shfl_xor_sync(0xFFFFFFFFu, sum, o);
        if (lane == 0) sred[grp * 4 + wig] = sum;
        __syncthreads();
        sum = sred[grp * 4 + 0] + sred[grp * 4 + 1] + sred[grp * 4 + 2] + sred[grp * 4 + 3];
        float alpha = ex / sum;

        int bp = 4 * s + (b >> 7);
        int tp = b & 127;
        size_t idx = (size_t)bp * (TT * NN) + tp * NN + n;
        out[idx] = data[idx] * alpha;
        __syncthreads();
    }
}

// ---------------------------------------------------------------------------
extern "C" void kernel_launch(void* const* d_in, const int* in_sizes, int n_in,
                              void* d_out, int out_size) {
    const float* data = (const float*)d_in[0];
    const float* h0 = (const float*)d_in[1];
    const float* Wx = (const float*)d_in[2];
    const float* Wh = (const float*)d_in[3];
    const float* bvec = (const float*)d_in[4];
    const float* W1 = (const float*)d_in[5];
    const float* b1 = (const float*)d_in[6];
    const float* W2 = (const float*)d_in[7];
    const float* b2 = (const float*)d_in[8];
    const float* Wv = (const float*)d_in[9];
    float* out = (float*)d_out;

    const int SM_RNN = (32768 + 2048 + 1024) * 4;        // 140 KB
    const int SM_ATT = (128 * 128 + 256 + 128 + 8) * 4;  // ~66 KB

    cudaFuncSetAttribute(k_rnn9, cudaFuncAttributeMaxDynamicSharedMemorySize, SM_RNN);
    cudaFuncSetAttribute(k_att3, cudaFuncAttributeMaxDynamicSharedMemorySize, SM_ATT);

    k_xw3<<<dim3((TT * BB) / 128, HH / 128), 256>>>(data, Wx, bvec);
    k_pre3<<<BB, 256>>>(data, W1, b1);
    k_rnn9<<<BB / 4, 512, SM_RNN>>>(h0, Wh);
    k_q3<<<(TT * BB) / 128, 256>>>(W2, b2);
    k_att3<<<BB * 2, 256, SM_ATT>>>(data, Wv, out);
}